// round 10
// baseline (speedup 1.0000x reference)
#include <cuda_runtime.h>
#include <cuda_fp16.h>
#include <math.h>
#include <stdint.h>

// Problem constants (fixed by the dataset)
#define NMAX   100032
#define EMAX   1600000
#define DIMF   128
#define DV4    32
#define SCANB  1024
#define NSCANB ((NMAX + SCANB - 1) / SCANB)

// Static scratch — double-buffered fp16 feature tables (race-free fusion)
__device__ __half2 g_tab0[NMAX * 64];
__device__ __half2 g_tab1[NMAX * 64];
__device__ float   g_csrc[NMAX];
__device__ float   g_cdst[NMAX];
__device__ int     g_deg[2 * NMAX];   // raw degrees (no self): [0..n) out, [n..2n) in
__device__ int     g_off[NMAX + 1];   // CSR row offsets (by dst)
__device__ int     g_cursor[NMAX];
__device__ int     g_csr_src[EMAX];
__device__ int     g_bsum[NSCANB];

static inline int cdiv(int a, int b) { return (a + b - 1) / b; }

// ---------------------------------------------------------------------------
// Degree count (g_deg zeroed by memset; self-loop handled as +1 in coefs)
// ---------------------------------------------------------------------------
__global__ void k_deg_count(const int* __restrict__ ei, int E, int n) {
    int i = blockIdx.x * blockDim.x + threadIdx.x;
    if (i < E) {
        atomicAdd(&g_deg[ei[i]], 1);
        atomicAdd(&g_deg[n + ei[E + i]], 1);
    }
}

// ---------------------------------------------------------------------------
// scan1: block-local exclusive scan of raw in-degree; also computes coefs.
// ---------------------------------------------------------------------------
__global__ void k_scan1(int n) {
    __shared__ int sh[SCANB];
    int t = threadIdx.x;
    int i = blockIdx.x * SCANB + t;
    int v = (i < n) ? g_deg[n + i] : 0;
    sh[t] = v;
    __syncthreads();
#pragma unroll
    for (int o = 1; o < SCANB; o <<= 1) {
        int add = (t >= o) ? sh[t - o] : 0;
        __syncthreads();
        sh[t] += add;
        __syncthreads();
    }
    if (i < n) {
        g_off[i] = sh[t] - v;                       // exclusive within block
        g_csrc[i] = rsqrtf((float)(g_deg[i] + 1));  // +1 = self loop
        g_cdst[i] = rsqrtf((float)(v + 1));
    }
    if (t == SCANB - 1) g_bsum[blockIdx.x] = sh[t];
}

// scan2+scan3 fused: each block serially prefixes the (<=98) block sums.
__global__ void k_scan3(int n, int E) {
    __shared__ int base_sh;
    int b = blockIdx.x;
    if (threadIdx.x == 0) {
        int run = 0;
        for (int k = 0; k < b; k++) run += g_bsum[k];
        base_sh = run;
        if (b == 0) g_off[n] = E;
    }
    __syncthreads();
    int i = b * SCANB + threadIdx.x;
    if (i < n) {
        int o = g_off[i] + base_sh;
        g_off[i] = o;
        g_cursor[i] = o;
    }
}

__global__ void k_fill(const int* __restrict__ ei, int E) {
    int i = blockIdx.x * blockDim.x + threadIdx.x;
    if (i < E) {
        int s = ei[i];
        int d = ei[E + i];
        int pos = atomicAdd(&g_cursor[d], 1);
        g_csr_src[pos] = s;
    }
}

// ---------------------------------------------------------------------------
// Layer-1 scale: g_tab0 = fp16(node_attr * c_src[row])
// ---------------------------------------------------------------------------
__global__ void k_scale(const float* __restrict__ x, int n) {
    int idx = blockIdx.x * blockDim.x + threadIdx.x;
    if (idx < n * DV4) {
        int row = idx >> 5;
        float c = g_csrc[row];
        float4 v = ((const float4*)x)[idx];
        __half2 h0 = __floats2half2_rn(v.x * c, v.y * c);
        __half2 h1 = __floats2half2_rn(v.z * c, v.w * c);
        uint2 o;
        o.x = *(uint32_t*)&h0;
        o.y = *(uint32_t*)&h1;
        ((uint2*)g_tab0)[idx] = o;
    }
}

// ---------------------------------------------------------------------------
// FUSED layer kernel: gather + fp16 GEMM (m16n8k16) + epilogue.
//   Reads table IN (IN_ALT ? g_tab1 : g_tab0), epilogue writes the OTHER
//   table (hidden layers) — double buffering removes the RAW race.
//   tile = 128 rows x 128 cols, 256 threads (8 warps), full K=128 in smem.
// ---------------------------------------------------------------------------
#define SROW 68   // smem row stride in words (136 halves)

__device__ __forceinline__ void mma_f16(float* c, const uint32_t* a,
                                        uint32_t b0, uint32_t b1) {
    asm volatile(
        "mma.sync.aligned.m16n8k16.row.col.f32.f16.f16.f32 "
        "{%0,%1,%2,%3}, {%4,%5,%6,%7}, {%8,%9}, {%0,%1,%2,%3};"
        : "+f"(c[0]), "+f"(c[1]), "+f"(c[2]), "+f"(c[3])
        : "r"(a[0]), "r"(a[1]), "r"(a[2]), "r"(a[3]), "r"(b0), "r"(b1));
}

__device__ __forceinline__ void acc8(float* a, uint4 u) {
    const __half2* hp = (const __half2*)&u;
#pragma unroll
    for (int q = 0; q < 4; q++) {
        float2 f = __half22float2(hp[q]);
        a[2 * q]     += f.x;
        a[2 * q + 1] += f.y;
    }
}

template <bool WRITE_SCALED, bool IN_ALT>
__global__ void __launch_bounds__(256)
k_layer(const float* __restrict__ W, const float* __restrict__ b,
        float* __restrict__ out, int n) {
    extern __shared__ uint32_t smem[];
    uint32_t* As = smem;                 // 128 x 68 words
    uint32_t* Bs = smem + 128 * SROW;    // 128 x 68 words (W^T, n-major)

    const __half2* tab_in  = IN_ALT ? g_tab1 : g_tab0;
    __half2*       tab_out = IN_ALT ? g_tab0 : g_tab1;

    const int tid  = threadIdx.x;
    const int warp = tid >> 5;
    const int lane = tid & 31;
    const int g    = lane >> 2;
    const int t4   = lane & 3;
    const int rowBase = blockIdx.x * 128;
    const int warpRow = warp * 16;

    // ---- Phase B: transpose W (128x128 fp32) into Bs fp16 n-major ----
    for (int i = tid; i < 128 * 32; i += 256) {
        int k  = i >> 5;
        int c4 = i & 31;
        float4 v = __ldg(&((const float4*)W)[k * DV4 + c4]);
        __half* bh = (__half*)Bs;
        int n0 = c4 * 4;
        bh[(n0 + 0) * 2 * SROW + k] = __float2half_rn(v.x);
        bh[(n0 + 1) * 2 * SROW + k] = __float2half_rn(v.y);
        bh[(n0 + 2) * 2 * SROW + k] = __float2half_rn(v.z);
        bh[(n0 + 3) * 2 * SROW + k] = __float2half_rn(v.w);
    }

    // ---- Phase G: gather 16 rows per warp into As ----
    {
        const int h   = lane >> 4;     // half-warp id (0/1)
        const int l16 = lane & 15;
        const uint4* tab = (const uint4*)tab_in;

#pragma unroll 1
        for (int p = 0; p < 8; p++) {
            int lr   = warpRow + p * 2 + h;
            int node = rowBase + lr;
            float a[8] = {0.f, 0.f, 0.f, 0.f, 0.f, 0.f, 0.f, 0.f};
            if (node < n) {
                acc8(a, __ldg(&tab[node * 16 + l16]));   // self loop
                int j   = g_off[node];
                int end = g_off[node + 1];
                for (; j + 4 <= end; j += 4) {
                    int s0 = __ldg(&g_csr_src[j]);
                    int s1 = __ldg(&g_csr_src[j + 1]);
                    int s2 = __ldg(&g_csr_src[j + 2]);
                    int s3 = __ldg(&g_csr_src[j + 3]);
                    uint4 v0 = __ldg(&tab[s0 * 16 + l16]);
                    uint4 v1 = __ldg(&tab[s1 * 16 + l16]);
                    uint4 v2 = __ldg(&tab[s2 * 16 + l16]);
                    uint4 v3 = __ldg(&tab[s3 * 16 + l16]);
                    acc8(a, v0); acc8(a, v1); acc8(a, v2); acc8(a, v3);
                }
                for (; j < end; j++) {
                    int s = __ldg(&g_csr_src[j]);
                    acc8(a, __ldg(&tab[s * 16 + l16]));
                }
                float cd = g_cdst[node];
#pragma unroll
                for (int q = 0; q < 8; q++) a[q] *= cd;
            }
            __half2 h0 = __floats2half2_rn(a[0], a[1]);
            __half2 h1 = __floats2half2_rn(a[2], a[3]);
            __half2 h2 = __floats2half2_rn(a[4], a[5]);
            __half2 h3 = __floats2half2_rn(a[6], a[7]);
            uint4 pk = make_uint4(*(uint32_t*)&h0, *(uint32_t*)&h1,
                                  *(uint32_t*)&h2, *(uint32_t*)&h3);
            ((uint4*)As)[lr * (SROW / 4) + l16] = pk;   // word = lr*68 + l16*4
        }
    }
    __syncthreads();

    // ---- Phase M: mma mainloop ----
    float acc[16][4];
#pragma unroll
    for (int nt = 0; nt < 16; nt++) {
        float b0v = __ldg(&b[nt * 8 + t4 * 2]);
        float b1v = __ldg(&b[nt * 8 + t4 * 2 + 1]);
        acc[nt][0] = b0v; acc[nt][1] = b1v;
        acc[nt][2] = b0v; acc[nt][3] = b1v;
    }

#pragma unroll
    for (int kc = 0; kc < 8; kc++) {
        uint32_t a[4];
        const int a0 = (warpRow + g) * SROW + kc * 8 + t4;
        const int a1 = a0 + 8 * SROW;
        a[0] = As[a0];
        a[1] = As[a1];
        a[2] = As[a0 + 4];
        a[3] = As[a1 + 4];
#pragma unroll
        for (int nt = 0; nt < 16; nt++) {
            const int bo = (nt * 8 + g) * SROW + kc * 8 + t4;
            mma_f16(acc[nt], a, Bs[bo], Bs[bo + 4]);
        }
    }

    // ---- epilogue ----
    const int r0 = rowBase + warpRow + g;
    const int r1 = r0 + 8;
#pragma unroll
    for (int nt = 0; nt < 16; nt++) {
        const int col = nt * 8 + t4 * 2;
        if (WRITE_SCALED) {
            if (r0 < n) {
                float cs = g_csrc[r0];
                tab_out[r0 * 64 + (col >> 1)] =
                    __floats2half2_rn(fmaxf(acc[nt][0], 0.f) * cs,
                                      fmaxf(acc[nt][1], 0.f) * cs);
            }
            if (r1 < n) {
                float cs = g_csrc[r1];
                tab_out[r1 * 64 + (col >> 1)] =
                    __floats2half2_rn(fmaxf(acc[nt][2], 0.f) * cs,
                                      fmaxf(acc[nt][3], 0.f) * cs);
            }
        } else {
            if (r0 < n)
                *(float2*)&out[r0 * DIMF + col] = make_float2(acc[nt][0], acc[nt][1]);
            if (r1 < n)
                *(float2*)&out[r1 * DIMF + col] = make_float2(acc[nt][2], acc[nt][3]);
        }
    }
}

// ---------------------------------------------------------------------------

#define SMEM_BYTES (2 * 128 * SROW * 4)   // 69632

extern "C" void kernel_launch(void* const* d_in, const int* in_sizes, int n_in,
                              void* d_out, int out_size) {
    const float* node_attr = (const float*)d_in[0];
    const float* W0 = (const float*)d_in[1];
    const float* b0 = (const float*)d_in[2];
    const float* W1 = (const float*)d_in[3];
    const float* b1 = (const float*)d_in[4];
    const float* W2 = (const float*)d_in[5];
    const float* b2 = (const float*)d_in[6];
    const int*   edge = (const int*)d_in[7];

    int n = in_sizes[0] / DIMF;   // 100000
    int E = in_sizes[7] / 2;      // 1600000
    int nb = cdiv(n, SCANB);

    cudaFuncSetAttribute(k_layer<true, false>,
                         cudaFuncAttributeMaxDynamicSharedMemorySize, SMEM_BYTES);
    cudaFuncSetAttribute(k_layer<true, true>,
                         cudaFuncAttributeMaxDynamicSharedMemorySize, SMEM_BYTES);
    cudaFuncSetAttribute(k_layer<false, false>,
                         cudaFuncAttributeMaxDynamicSharedMemorySize, SMEM_BYTES);

    // degrees (memset) + count + coefs/scan + CSR
    void* degPtr;
    cudaGetSymbolAddress(&degPtr, g_deg);
    cudaMemsetAsync(degPtr, 0, 2 * n * sizeof(int));
    k_deg_count<<<cdiv(E, 256), 256>>>(edge, E, n);
    k_scan1<<<nb, SCANB>>>(n);
    k_scan3<<<nb, SCANB>>>(n, E);
    k_fill<<<cdiv(E, 256), 256>>>(edge, E);

    // layer-1 table (writes g_tab0)
    k_scale<<<cdiv(n * DV4, 256), 256>>>(node_attr, n);

    int grid = cdiv(n, 128);
    // L1: read tab0 -> write tab1 ; L2: read tab1 -> write tab0 ; L3: read tab0 -> out
    k_layer<true,  false><<<grid, 256, SMEM_BYTES>>>(W0, b0, nullptr, n);
    k_layer<true,  true ><<<grid, 256, SMEM_BYTES>>>(W1, b1, nullptr, n);
    k_layer<false, false><<<grid, 256, SMEM_BYTES>>>(W2, b2, (float*)d_out, n);
}

// round 11
// speedup vs baseline: 1.1450x; 1.1450x over previous
#include <cuda_runtime.h>
#include <cuda_fp16.h>
#include <math.h>
#include <stdint.h>

// Problem constants (fixed by the dataset)
#define NMAX   100032
#define EMAX   1600000
#define DIMF   128
#define DV4    32
#define SCANB  1024
#define NSCANB ((NMAX + SCANB - 1) / SCANB)

// Static scratch
__device__ __half2 g_tab[NMAX * 64];    // scaled features fp16 (gather table)
__device__ __half2 g_aggh[NMAX * 64];   // gathered+c_dst-scaled rows, fp16
__device__ float   g_csrc[NMAX];
__device__ float   g_cdst[NMAX];
__device__ int     g_deg[2 * NMAX];     // raw degrees: [0..n) out, [n..2n) in
__device__ int     g_off[NMAX + 1];     // CSR row offsets (by dst)
__device__ int     g_cursor[NMAX];
__device__ int     g_csr_src[EMAX];
__device__ int     g_bsum[NSCANB];

static inline int cdiv(int a, int b) { return (a + b - 1) / b; }

// ---------------------------------------------------------------------------
// Degree count (g_deg zeroed by memset; self-loop handled as +1 in coefs)
// ---------------------------------------------------------------------------
__global__ void k_deg_count(const int* __restrict__ ei, int E, int n) {
    int i = blockIdx.x * blockDim.x + threadIdx.x;
    if (i < E) {
        atomicAdd(&g_deg[ei[i]], 1);
        atomicAdd(&g_deg[n + ei[E + i]], 1);
    }
}

// ---------------------------------------------------------------------------
// scan1: block-local exclusive scan of raw in-degree; also computes coefs.
// ---------------------------------------------------------------------------
__global__ void k_scan1(int n) {
    __shared__ int sh[SCANB];
    int t = threadIdx.x;
    int i = blockIdx.x * SCANB + t;
    int v = (i < n) ? g_deg[n + i] : 0;
    sh[t] = v;
    __syncthreads();
#pragma unroll
    for (int o = 1; o < SCANB; o <<= 1) {
        int add = (t >= o) ? sh[t - o] : 0;
        __syncthreads();
        sh[t] += add;
        __syncthreads();
    }
    if (i < n) {
        g_off[i] = sh[t] - v;                       // exclusive within block
        g_csrc[i] = rsqrtf((float)(g_deg[i] + 1));  // +1 = self loop
        g_cdst[i] = rsqrtf((float)(v + 1));
    }
    if (t == SCANB - 1) g_bsum[blockIdx.x] = sh[t];
}

// scan2+scan3 fused: each block serially prefixes the (<=98) block sums.
__global__ void k_scan3(int n, int E) {
    __shared__ int base_sh;
    int b = blockIdx.x;
    if (threadIdx.x == 0) {
        int run = 0;
        for (int k = 0; k < b; k++) run += g_bsum[k];
        base_sh = run;
        if (b == 0) g_off[n] = E;
    }
    __syncthreads();
    int i = b * SCANB + threadIdx.x;
    if (i < n) {
        int o = g_off[i] + base_sh;
        g_off[i] = o;
        g_cursor[i] = o;
    }
}

__global__ void k_fill(const int* __restrict__ ei, int E) {
    int i = blockIdx.x * blockDim.x + threadIdx.x;
    if (i < E) {
        int s = ei[i];
        int d = ei[E + i];
        int pos = atomicAdd(&g_cursor[d], 1);
        g_csr_src[pos] = s;
    }
}

// ---------------------------------------------------------------------------
// Layer-1 scale: g_tab = fp16(node_attr * c_src[row])
// ---------------------------------------------------------------------------
__global__ void k_scale(const float* __restrict__ x, int n) {
    int idx = blockIdx.x * blockDim.x + threadIdx.x;
    if (idx < n * DV4) {
        int row = idx >> 5;
        float c = g_csrc[row];
        float4 v = ((const float4*)x)[idx];
        __half2 h0 = __floats2half2_rn(v.x * c, v.y * c);
        __half2 h1 = __floats2half2_rn(v.z * c, v.w * c);
        uint2 o;
        o.x = *(uint32_t*)&h0;
        o.y = *(uint32_t*)&h1;
        ((uint2*)g_tab)[idx] = o;
    }
}

// ---------------------------------------------------------------------------
// Gather: g_aggh[d,:] = fp16( c_dst[d] * (tab[d,:] + sum_{s in in(d)} tab[s,:]) )
// 16 lanes per node (fp16 row = 256B = 16 x uint4), fp32 accumulation,
// unroll-4 edges -> 8 outstanding 256B loads per warp. High occupancy.
// ---------------------------------------------------------------------------
__device__ __forceinline__ void acc8(float* a, uint4 u) {
    const __half2* hp = (const __half2*)&u;
#pragma unroll
    for (int q = 0; q < 4; q++) {
        float2 f = __half22float2(hp[q]);
        a[2 * q]     += f.x;
        a[2 * q + 1] += f.y;
    }
}

__global__ void __launch_bounds__(256)
k_gather(int n) {
    int t = blockIdx.x * blockDim.x + threadIdx.x;
    int node = t >> 4;
    int l16  = t & 15;
    if (node >= n) return;

    const uint4* tab = (const uint4*)g_tab;
    float a[8] = {0.f, 0.f, 0.f, 0.f, 0.f, 0.f, 0.f, 0.f};
    acc8(a, __ldg(&tab[node * 16 + l16]));   // self loop

    int j   = g_off[node];
    int end = g_off[node + 1];
    for (; j + 4 <= end; j += 4) {
        int s0 = __ldg(&g_csr_src[j]);
        int s1 = __ldg(&g_csr_src[j + 1]);
        int s2 = __ldg(&g_csr_src[j + 2]);
        int s3 = __ldg(&g_csr_src[j + 3]);
        uint4 v0 = __ldg(&tab[s0 * 16 + l16]);
        uint4 v1 = __ldg(&tab[s1 * 16 + l16]);
        uint4 v2 = __ldg(&tab[s2 * 16 + l16]);
        uint4 v3 = __ldg(&tab[s3 * 16 + l16]);
        acc8(a, v0); acc8(a, v1); acc8(a, v2); acc8(a, v3);
    }
    for (; j < end; j++) {
        int s = __ldg(&g_csr_src[j]);
        acc8(a, __ldg(&tab[s * 16 + l16]));
    }

    float cd = g_cdst[node];
#pragma unroll
    for (int q = 0; q < 8; q++) a[q] *= cd;

    __half2 h0 = __floats2half2_rn(a[0], a[1]);
    __half2 h1 = __floats2half2_rn(a[2], a[3]);
    __half2 h2 = __floats2half2_rn(a[4], a[5]);
    __half2 h3 = __floats2half2_rn(a[6], a[7]);
    uint4 pk = make_uint4(*(uint32_t*)&h0, *(uint32_t*)&h1,
                          *(uint32_t*)&h2, *(uint32_t*)&h3);
    ((uint4*)g_aggh)[node * 16 + l16] = pk;
}

// ---------------------------------------------------------------------------
// fp16 GEMM (m16n8k16): y = aggh @ W + b ; full K=128 in smem.
//   WRITE_SCALED: g_tab = fp16(relu(y)*c_src) ; else out = y (fp32).
// Block 256 threads (8 warps), tile 128x128. A-load = raw uint4 copy.
// ---------------------------------------------------------------------------
#define SROW 68   // smem row stride in words (136 halves)

__device__ __forceinline__ void mma_f16(float* c, const uint32_t* a,
                                        uint32_t b0, uint32_t b1) {
    asm volatile(
        "mma.sync.aligned.m16n8k16.row.col.f32.f16.f16.f32 "
        "{%0,%1,%2,%3}, {%4,%5,%6,%7}, {%8,%9}, {%0,%1,%2,%3};"
        : "+f"(c[0]), "+f"(c[1]), "+f"(c[2]), "+f"(c[3])
        : "r"(a[0]), "r"(a[1]), "r"(a[2]), "r"(a[3]), "r"(b0), "r"(b1));
}

template <bool WRITE_SCALED>
__global__ void __launch_bounds__(256)
k_gemm(const float* __restrict__ W, const float* __restrict__ b,
       float* __restrict__ out, int n) {
    extern __shared__ uint32_t smem[];
    uint32_t* As = smem;                 // 128 x 68 words (fp16 rows)
    uint32_t* Bs = smem + 128 * SROW;    // 128 x 68 words (W^T, n-major fp16)

    const int tid  = threadIdx.x;
    const int warp = tid >> 5;
    const int lane = tid & 31;
    const int g    = lane >> 2;
    const int t4   = lane & 3;
    const int rowBase = blockIdx.x * 128;
    const int warpRow = warp * 16;

    // ---- A: copy 128 fp16 rows from g_aggh (2048 uint4, 8 per thread) ----
    {
        const uint4* src = (const uint4*)g_aggh;
#pragma unroll
        for (int it = 0; it < 8; it++) {
            int i  = tid + it * 256;
            int r  = i >> 4;
            int c4 = i & 15;
            int gr = rowBase + r;
            uint4 v = make_uint4(0u, 0u, 0u, 0u);
            if (gr < n) v = __ldg(&src[gr * 16 + c4]);
            ((uint4*)As)[r * (SROW / 4) + c4] = v;
        }
    }
    // ---- B: transpose W (128x128 fp32) into Bs fp16 n-major ----
    for (int i = tid; i < 128 * 32; i += 256) {
        int k  = i >> 5;
        int c4 = i & 31;
        float4 v = __ldg(&((const float4*)W)[k * DV4 + c4]);
        __half* bh = (__half*)Bs;
        int n0 = c4 * 4;
        bh[(n0 + 0) * 2 * SROW + k] = __float2half_rn(v.x);
        bh[(n0 + 1) * 2 * SROW + k] = __float2half_rn(v.y);
        bh[(n0 + 2) * 2 * SROW + k] = __float2half_rn(v.z);
        bh[(n0 + 3) * 2 * SROW + k] = __float2half_rn(v.w);
    }
    __syncthreads();

    // ---- mma mainloop ----
    float acc[16][4];
#pragma unroll
    for (int nt = 0; nt < 16; nt++) {
        float b0v = __ldg(&b[nt * 8 + t4 * 2]);
        float b1v = __ldg(&b[nt * 8 + t4 * 2 + 1]);
        acc[nt][0] = b0v; acc[nt][1] = b1v;
        acc[nt][2] = b0v; acc[nt][3] = b1v;
    }

#pragma unroll
    for (int kc = 0; kc < 8; kc++) {
        uint32_t a[4];
        const int a0 = (warpRow + g) * SROW + kc * 8 + t4;
        const int a1 = a0 + 8 * SROW;
        a[0] = As[a0];
        a[1] = As[a1];
        a[2] = As[a0 + 4];
        a[3] = As[a1 + 4];
#pragma unroll
        for (int nt = 0; nt < 16; nt++) {
            const int bo = (nt * 8 + g) * SROW + kc * 8 + t4;
            mma_f16(acc[nt], a, Bs[bo], Bs[bo + 4]);
        }
    }

    // ---- epilogue ----
    const int r0 = rowBase + warpRow + g;
    const int r1 = r0 + 8;
#pragma unroll
    for (int nt = 0; nt < 16; nt++) {
        const int col = nt * 8 + t4 * 2;
        if (WRITE_SCALED) {
            if (r0 < n) {
                float cs = g_csrc[r0];
                g_tab[r0 * 64 + (col >> 1)] =
                    __floats2half2_rn(fmaxf(acc[nt][0], 0.f) * cs,
                                      fmaxf(acc[nt][1], 0.f) * cs);
            }
            if (r1 < n) {
                float cs = g_csrc[r1];
                g_tab[r1 * 64 + (col >> 1)] =
                    __floats2half2_rn(fmaxf(acc[nt][2], 0.f) * cs,
                                      fmaxf(acc[nt][3], 0.f) * cs);
            }
        } else {
            if (r0 < n)
                *(float2*)&out[r0 * DIMF + col] = make_float2(acc[nt][0], acc[nt][1]);
            if (r1 < n)
                *(float2*)&out[r1 * DIMF + col] = make_float2(acc[nt][2], acc[nt][3]);
        }
    }
}

// ---------------------------------------------------------------------------

#define SMEM_BYTES (2 * 128 * SROW * 4)   // 69632

extern "C" void kernel_launch(void* const* d_in, const int* in_sizes, int n_in,
                              void* d_out, int out_size) {
    const float* node_attr = (const float*)d_in[0];
    const float* W0 = (const float*)d_in[1];
    const float* b0 = (const float*)d_in[2];
    const float* W1 = (const float*)d_in[3];
    const float* b1 = (const float*)d_in[4];
    const float* W2 = (const float*)d_in[5];
    const float* b2 = (const float*)d_in[6];
    const int*   edge = (const int*)d_in[7];

    int n = in_sizes[0] / DIMF;   // 100000
    int E = in_sizes[7] / 2;      // 1600000
    int nb = cdiv(n, SCANB);

    cudaFuncSetAttribute(k_gemm<true>,
                         cudaFuncAttributeMaxDynamicSharedMemorySize, SMEM_BYTES);
    cudaFuncSetAttribute(k_gemm<false>,
                         cudaFuncAttributeMaxDynamicSharedMemorySize, SMEM_BYTES);

    // degrees (memset) + count + coefs/scan + CSR
    void* degPtr;
    cudaGetSymbolAddress(&degPtr, g_deg);
    cudaMemsetAsync(degPtr, 0, 2 * n * sizeof(int));
    k_deg_count<<<cdiv(E, 256), 256>>>(edge, E, n);
    k_scan1<<<nb, SCANB>>>(n);
    k_scan3<<<nb, SCANB>>>(n, E);
    k_fill<<<cdiv(E, 256), 256>>>(edge, E);

    // layer-1 table
    k_scale<<<cdiv(n * DV4, 256), 256>>>(node_attr, n);

    int ggrid = cdiv(n * 16, 256);
    int mgrid = cdiv(n, 128);

    k_gather<<<ggrid, 256>>>(n);
    k_gemm<true><<<mgrid, 256, SMEM_BYTES>>>(W0, b0, nullptr, n);
    k_gather<<<ggrid, 256>>>(n);
    k_gemm<true><<<mgrid, 256, SMEM_BYTES>>>(W1, b1, nullptr, n);
    k_gather<<<ggrid, 256>>>(n);
    k_gemm<false><<<mgrid, 256, SMEM_BYTES>>>(W2, b2, (float*)d_out, n);
}

// round 12
// speedup vs baseline: 1.4651x; 1.2796x over previous
#include <cuda_runtime.h>
#include <cuda_fp16.h>
#include <math.h>
#include <stdint.h>

// Problem constants (fixed by the dataset)
#define NMAX   100032
#define EMAX   1600000
#define DIMF   128
#define DV4    32
#define SCANB  1024
#define NSCANB ((NMAX + SCANB - 1) / SCANB)

// Static scratch
__device__ __half2 g_tab[NMAX * 64];    // scaled features fp16 (gather table)
__device__ __half2 g_aggh[NMAX * 64];   // gathered+c_dst-scaled rows, fp16
__device__ __half  g_W16[3 * DIMF * DIMF]; // fp16 n-major weights (k contiguous)
__device__ float   g_csrc[NMAX];
__device__ float   g_cdst[NMAX];
__device__ int     g_deg[2 * NMAX];     // raw degrees: [0..n) out, [n..2n) in
__device__ int     g_off[NMAX + 1];     // CSR row offsets (by dst)
__device__ int     g_cursor[NMAX];
__device__ int     g_csr_src[EMAX];
__device__ int     g_bsum[NSCANB];

static inline int cdiv(int a, int b) { return (a + b - 1) / b; }

// ---------------------------------------------------------------------------
// W prep: fp32 k-major [k][n] -> fp16 n-major [n][k], one-time.
// grid (2,2,3): 64x64 tile per block, smem transpose.
// ---------------------------------------------------------------------------
__global__ void k_prepW(const float* __restrict__ W0,
                        const float* __restrict__ W1,
                        const float* __restrict__ W2) {
    __shared__ float t[64][65];
    const float* W = (blockIdx.z == 0) ? W0 : (blockIdx.z == 1) ? W1 : W2;
    __half* out = g_W16 + blockIdx.z * DIMF * DIMF;
    const int tid = threadIdx.x;
    const int kt = blockIdx.x * 64;
    const int nt = blockIdx.y * 64;

#pragma unroll
    for (int it = 0; it < 4; it++) {
        int i  = tid + it * 256;      // 1024 float4 = 64 rows x 16 float4
        int r  = i >> 4;              // k-local
        int c4 = i & 15;              // n-local float4
        float4 v = __ldg(&((const float4*)W)[(kt + r) * DV4 + blockIdx.y * 16 + c4]);
        t[r][c4 * 4 + 0] = v.x;
        t[r][c4 * 4 + 1] = v.y;
        t[r][c4 * 4 + 2] = v.z;
        t[r][c4 * 4 + 3] = v.w;
    }
    __syncthreads();
#pragma unroll
    for (int it = 0; it < 4; it++) {
        int i  = tid + it * 256;
        int r  = i >> 4;              // n-local
        int c4 = i & 15;              // k-local group of 4
        __half2 h0 = __floats2half2_rn(t[c4 * 4 + 0][r], t[c4 * 4 + 1][r]);
        __half2 h1 = __floats2half2_rn(t[c4 * 4 + 2][r], t[c4 * 4 + 3][r]);
        uint2 o;
        o.x = *(uint32_t*)&h0;
        o.y = *(uint32_t*)&h1;
        *(uint2*)(out + (nt + r) * DIMF + kt + c4 * 4) = o;
    }
}

// ---------------------------------------------------------------------------
// Degree count, x4 vectorized (E divisible by 4; g_deg pre-zeroed)
// ---------------------------------------------------------------------------
__global__ void k_deg_count(const int* __restrict__ ei, int E, int n) {
    int i = blockIdx.x * blockDim.x + threadIdx.x;
    if (i * 4 < E) {
        int4 s = ((const int4*)ei)[i];
        int4 d = ((const int4*)(ei + E))[i];
        atomicAdd(&g_deg[s.x], 1);
        atomicAdd(&g_deg[s.y], 1);
        atomicAdd(&g_deg[s.z], 1);
        atomicAdd(&g_deg[s.w], 1);
        atomicAdd(&g_deg[n + d.x], 1);
        atomicAdd(&g_deg[n + d.y], 1);
        atomicAdd(&g_deg[n + d.z], 1);
        atomicAdd(&g_deg[n + d.w], 1);
    }
}

// ---------------------------------------------------------------------------
// scan1: block-local exclusive scan of raw in-degree; also computes coefs.
// ---------------------------------------------------------------------------
__global__ void k_scan1(int n) {
    __shared__ int sh[SCANB];
    int t = threadIdx.x;
    int i = blockIdx.x * SCANB + t;
    int v = (i < n) ? g_deg[n + i] : 0;
    sh[t] = v;
    __syncthreads();
#pragma unroll
    for (int o = 1; o < SCANB; o <<= 1) {
        int add = (t >= o) ? sh[t - o] : 0;
        __syncthreads();
        sh[t] += add;
        __syncthreads();
    }
    if (i < n) {
        g_off[i] = sh[t] - v;                       // exclusive within block
        g_csrc[i] = rsqrtf((float)(g_deg[i] + 1));  // +1 = self loop
        g_cdst[i] = rsqrtf((float)(v + 1));
    }
    if (t == SCANB - 1) g_bsum[blockIdx.x] = sh[t];
}

// scan2+scan3 fused: each block serially prefixes the (<=98) block sums.
__global__ void k_scan3(int n, int E) {
    __shared__ int base_sh;
    int b = blockIdx.x;
    if (threadIdx.x == 0) {
        int run = 0;
        for (int k = 0; k < b; k++) run += g_bsum[k];
        base_sh = run;
        if (b == 0) g_off[n] = E;
    }
    __syncthreads();
    int i = b * SCANB + threadIdx.x;
    if (i < n) {
        int o = g_off[i] + base_sh;
        g_off[i] = o;
        g_cursor[i] = o;
    }
}

// CSR fill, x4 vectorized
__global__ void k_fill(const int* __restrict__ ei, int E) {
    int i = blockIdx.x * blockDim.x + threadIdx.x;
    if (i * 4 < E) {
        int4 s = ((const int4*)ei)[i];
        int4 d = ((const int4*)(ei + E))[i];
        int p0 = atomicAdd(&g_cursor[d.x], 1);
        int p1 = atomicAdd(&g_cursor[d.y], 1);
        int p2 = atomicAdd(&g_cursor[d.z], 1);
        int p3 = atomicAdd(&g_cursor[d.w], 1);
        g_csr_src[p0] = s.x;
        g_csr_src[p1] = s.y;
        g_csr_src[p2] = s.z;
        g_csr_src[p3] = s.w;
    }
}

// ---------------------------------------------------------------------------
// Layer-1 scale: g_tab = fp16(node_attr * c_src[row])
// ---------------------------------------------------------------------------
__global__ void k_scale(const float* __restrict__ x, int n) {
    int idx = blockIdx.x * blockDim.x + threadIdx.x;
    if (idx < n * DV4) {
        int row = idx >> 5;
        float c = g_csrc[row];
        float4 v = ((const float4*)x)[idx];
        __half2 h0 = __floats2half2_rn(v.x * c, v.y * c);
        __half2 h1 = __floats2half2_rn(v.z * c, v.w * c);
        uint2 o;
        o.x = *(uint32_t*)&h0;
        o.y = *(uint32_t*)&h1;
        ((uint2*)g_tab)[idx] = o;
    }
}

// ---------------------------------------------------------------------------
// Gather: g_aggh[d,:] = fp16( c_dst[d] * (tab[d,:] + sum_{s in in(d)} tab[s,:]) )
// 16 lanes per node (fp16 row = 256B = 16 x uint4), fp32 accumulation.
// ---------------------------------------------------------------------------
__device__ __forceinline__ void acc8(float* a, uint4 u) {
    const __half2* hp = (const __half2*)&u;
#pragma unroll
    for (int q = 0; q < 4; q++) {
        float2 f = __half22float2(hp[q]);
        a[2 * q]     += f.x;
        a[2 * q + 1] += f.y;
    }
}

__global__ void __launch_bounds__(256)
k_gather(int n) {
    int t = blockIdx.x * blockDim.x + threadIdx.x;
    int node = t >> 4;
    int l16  = t & 15;
    if (node >= n) return;

    const uint4* tab = (const uint4*)g_tab;
    float a[8] = {0.f, 0.f, 0.f, 0.f, 0.f, 0.f, 0.f, 0.f};
    acc8(a, __ldg(&tab[node * 16 + l16]));   // self loop

    int j   = g_off[node];
    int end = g_off[node + 1];
    for (; j + 4 <= end; j += 4) {
        int s0 = __ldg(&g_csr_src[j]);
        int s1 = __ldg(&g_csr_src[j + 1]);
        int s2 = __ldg(&g_csr_src[j + 2]);
        int s3 = __ldg(&g_csr_src[j + 3]);
        uint4 v0 = __ldg(&tab[s0 * 16 + l16]);
        uint4 v1 = __ldg(&tab[s1 * 16 + l16]);
        uint4 v2 = __ldg(&tab[s2 * 16 + l16]);
        uint4 v3 = __ldg(&tab[s3 * 16 + l16]);
        acc8(a, v0); acc8(a, v1); acc8(a, v2); acc8(a, v3);
    }
    for (; j < end; j++) {
        int s = __ldg(&g_csr_src[j]);
        acc8(a, __ldg(&tab[s * 16 + l16]));
    }

    float cd = g_cdst[node];
#pragma unroll
    for (int q = 0; q < 8; q++) a[q] *= cd;

    __half2 h0 = __floats2half2_rn(a[0], a[1]);
    __half2 h1 = __floats2half2_rn(a[2], a[3]);
    __half2 h2 = __floats2half2_rn(a[4], a[5]);
    __half2 h3 = __floats2half2_rn(a[6], a[7]);
    uint4 pk = make_uint4(*(uint32_t*)&h0, *(uint32_t*)&h1,
                          *(uint32_t*)&h2, *(uint32_t*)&h3);
    ((uint4*)g_aggh)[node * 16 + l16] = pk;
}

// ---------------------------------------------------------------------------
// fp16 GEMM (m16n8k16): y = aggh @ W + b ; full K=128 in smem.
//   WRITE_SCALED: g_tab = fp16(relu(y)*c_src) ; else out = y (fp32).
// Block 256 threads (8 warps), tile 128x128. A and B loads are uint4 copies.
// ---------------------------------------------------------------------------
#define SROW 68   // smem row stride in words (136 halves)

__device__ __forceinline__ void mma_f16(float* c, const uint32_t* a,
                                        uint32_t b0, uint32_t b1) {
    asm volatile(
        "mma.sync.aligned.m16n8k16.row.col.f32.f16.f16.f32 "
        "{%0,%1,%2,%3}, {%4,%5,%6,%7}, {%8,%9}, {%0,%1,%2,%3};"
        : "+f"(c[0]), "+f"(c[1]), "+f"(c[2]), "+f"(c[3])
        : "r"(a[0]), "r"(a[1]), "r"(a[2]), "r"(a[3]), "r"(b0), "r"(b1));
}

template <bool WRITE_SCALED>
__global__ void __launch_bounds__(256)
k_gemm(const __half* __restrict__ W16, const float* __restrict__ b,
       float* __restrict__ out, int n) {
    extern __shared__ uint32_t smem[];
    uint32_t* As = smem;                 // 128 x 68 words (fp16 rows)
    uint32_t* Bs = smem + 128 * SROW;    // 128 x 68 words (W^T, n-major fp16)

    const int tid  = threadIdx.x;
    const int warp = tid >> 5;
    const int lane = tid & 31;
    const int g    = lane >> 2;
    const int t4   = lane & 3;
    const int rowBase = blockIdx.x * 128;
    const int warpRow = warp * 16;

    // ---- A: copy 128 fp16 rows from g_aggh ----
    {
        const uint4* src = (const uint4*)g_aggh;
#pragma unroll
        for (int it = 0; it < 8; it++) {
            int i  = tid + it * 256;
            int r  = i >> 4;
            int c4 = i & 15;
            int gr = rowBase + r;
            uint4 v = make_uint4(0u, 0u, 0u, 0u);
            if (gr < n) v = __ldg(&src[gr * 16 + c4]);
            ((uint4*)As)[r * (SROW / 4) + c4] = v;
        }
    }
    // ---- B: copy prepped fp16 n-major W ----
    {
        const uint4* src = (const uint4*)W16;
#pragma unroll
        for (int it = 0; it < 8; it++) {
            int i  = tid + it * 256;
            int r  = i >> 4;
            int c4 = i & 15;
            ((uint4*)Bs)[r * (SROW / 4) + c4] = __ldg(&src[r * 16 + c4]);
        }
    }
    __syncthreads();

    // ---- mma mainloop ----
    float acc[16][4];
#pragma unroll
    for (int nt = 0; nt < 16; nt++) {
        float b0v = __ldg(&b[nt * 8 + t4 * 2]);
        float b1v = __ldg(&b[nt * 8 + t4 * 2 + 1]);
        acc[nt][0] = b0v; acc[nt][1] = b1v;
        acc[nt][2] = b0v; acc[nt][3] = b1v;
    }

#pragma unroll
    for (int kc = 0; kc < 8; kc++) {
        uint32_t a[4];
        const int a0 = (warpRow + g) * SROW + kc * 8 + t4;
        const int a1 = a0 + 8 * SROW;
        a[0] = As[a0];
        a[1] = As[a1];
        a[2] = As[a0 + 4];
        a[3] = As[a1 + 4];
#pragma unroll
        for (int nt = 0; nt < 16; nt++) {
            const int bo = (nt * 8 + g) * SROW + kc * 8 + t4;
            mma_f16(acc[nt], a, Bs[bo], Bs[bo + 4]);
        }
    }

    // ---- epilogue ----
    const int r0 = rowBase + warpRow + g;
    const int r1 = r0 + 8;
#pragma unroll
    for (int nt = 0; nt < 16; nt++) {
        const int col = nt * 8 + t4 * 2;
        if (WRITE_SCALED) {
            if (r0 < n) {
                float cs = g_csrc[r0];
                g_tab[r0 * 64 + (col >> 1)] =
                    __floats2half2_rn(fmaxf(acc[nt][0], 0.f) * cs,
                                      fmaxf(acc[nt][1], 0.f) * cs);
            }
            if (r1 < n) {
                float cs = g_csrc[r1];
                g_tab[r1 * 64 + (col >> 1)] =
                    __floats2half2_rn(fmaxf(acc[nt][2], 0.f) * cs,
                                      fmaxf(acc[nt][3], 0.f) * cs);
            }
        } else {
            if (r0 < n)
                *(float2*)&out[r0 * DIMF + col] = make_float2(acc[nt][0], acc[nt][1]);
            if (r1 < n)
                *(float2*)&out[r1 * DIMF + col] = make_float2(acc[nt][2], acc[nt][3]);
        }
    }
}

// ---------------------------------------------------------------------------

#define SMEM_BYTES (2 * 128 * SROW * 4)   // 69632

extern "C" void kernel_launch(void* const* d_in, const int* in_sizes, int n_in,
                              void* d_out, int out_size) {
    const float* node_attr = (const float*)d_in[0];
    const float* W0 = (const float*)d_in[1];
    const float* b0 = (const float*)d_in[2];
    const float* W1 = (const float*)d_in[3];
    const float* b1 = (const float*)d_in[4];
    const float* W2 = (const float*)d_in[5];
    const float* b2 = (const float*)d_in[6];
    const int*   edge = (const int*)d_in[7];

    int n = in_sizes[0] / DIMF;   // 100000
    int E = in_sizes[7] / 2;      // 1600000
    int nb = cdiv(n, SCANB);

    cudaFuncSetAttribute(k_gemm<true>,
                         cudaFuncAttributeMaxDynamicSharedMemorySize, SMEM_BYTES);
    cudaFuncSetAttribute(k_gemm<false>,
                         cudaFuncAttributeMaxDynamicSharedMemorySize, SMEM_BYTES);

    // one-time W conversion (independent of graph work)
    k_prepW<<<dim3(2, 2, 3), 256>>>(W0, W1, W2);

    // degrees (memset) + count + coefs/scan + CSR
    void* degPtr;
    cudaGetSymbolAddress(&degPtr, g_deg);
    cudaMemsetAsync(degPtr, 0, 2 * n * sizeof(int));
    k_deg_count<<<cdiv(E / 4, 256), 256>>>(edge, E, n);
    k_scan1<<<nb, SCANB>>>(n);
    k_scan3<<<nb, SCANB>>>(n, E);
    k_fill<<<cdiv(E / 4, 256), 256>>>(edge, E);

    // layer-1 table
    k_scale<<<cdiv(n * DV4, 256), 256>>>(node_attr, n);

    __half* w16;
    cudaGetSymbolAddress((void**)&w16, g_W16);

    int ggrid = cdiv(n * 16, 256);
    int mgrid = cdiv(n, 128);

    k_gather<<<ggrid, 256>>>(n);
    k_gemm<true><<<mgrid, 256, SMEM_BYTES>>>(w16, b0, nullptr, n);
    k_gather<<<ggrid, 256>>>(n);
    k_gemm<true><<<mgrid, 256, SMEM_BYTES>>>(w16 + DIMF * DIMF, b1, nullptr, n);
    k_gather<<<ggrid, 256>>>(n);
    k_gemm<false><<<mgrid, 256, SMEM_BYTES>>>(w16 + 2 * DIMF * DIMF, b2, (float*)d_out, n);
}